// round 1
// baseline (speedup 1.0000x reference)
#include <cuda_runtime.h>

#define T_STEPS 1000
#define C_CH    3
#define H_DIM   64
#define W_DIM   64
#define HW      (H_DIM * W_DIM)       // 4096
#define PIX     (C_CH * HW)           // 12288
#define NSEG    25
#define SEGLEN  (T_STEPS / NSEG)      // 40

// Scratch: et_updated values for one outer iteration, and per-segment partial sums.
__device__ float g_E[(size_t)T_STEPS * PIX];      // ~49 MB
__device__ float g_Psum[NSEG * PIX];              // ~1.2 MB

// ---------------------------------------------------------------------------
// Kernel A: for a (segment, 16x16 spatial tile), loop t over the segment:
//   stage the 18x18x3 input halo tile in shared, compute the 3x3 conv for all
//   3 output channels per thread, add temb[t_rev], scale by et_coeff, store to
//   g_E, and accumulate the per-segment partial sum.
// ---------------------------------------------------------------------------
__global__ __launch_bounds__(256) void conv_partial_kernel(
    const float* __restrict__ src,       // images 0..T-1 used, (.., C, H, W)
    const float* __restrict__ conv_w,    // (3,3,3,3) = 81
    const float* __restrict__ temb,      // (T, 3)
    const int*   __restrict__ t_arr,     // (T,)  = T-1 - j
    const float* __restrict__ et_coeff)  // (T,)
{
    __shared__ float s_in[3][18][20];    // padded row stride to spread banks

    const int seg  = blockIdx.y;
    const int tile = blockIdx.x;         // 0..15 : 4x4 tiling of 64x64
    const int th0  = (tile >> 2) * 16;
    const int tw0  = (tile &  3) * 16;
    const int tid  = threadIdx.x;
    const int ty   = tid >> 4;           // 0..15
    const int tx   = tid & 15;           // 0..15

    // Weights: loop-invariant across the t loop -> keep in registers.
    float w[81];
#pragma unroll
    for (int i = 0; i < 81; i++) w[i] = __ldg(conv_w + i);

    float ps0 = 0.f, ps1 = 0.f, ps2 = 0.f;
    const int t0 = seg * SEGLEN;
    const int pout = (th0 + ty) * W_DIM + (tw0 + tx);

    for (int j = t0; j < t0 + SEGLEN; j++) {
        // ---- stage input tile (with zero halo) ----
        const float* img = src + (size_t)j * PIX;
        for (int l = tid; l < 3 * 18 * 18; l += 256) {
            int ci  = l / 324;
            int rem = l - ci * 324;
            int r   = rem / 18;
            int c   = rem - r * 18;
            int gh  = th0 + r - 1;
            int gw  = tw0 + c - 1;
            float v = 0.f;
            if (gh >= 0 && gh < H_DIM && gw >= 0 && gw < W_DIM)
                v = img[ci * HW + gh * W_DIM + gw];
            s_in[ci][r][c] = v;
        }
        __syncthreads();

        // ---- gather 27 inputs, reuse across the 3 output channels ----
        float in[27];
#pragma unroll
        for (int ci = 0; ci < 3; ci++)
#pragma unroll
            for (int dh = 0; dh < 3; dh++)
#pragma unroll
                for (int dw = 0; dw < 3; dw++)
                    in[ci * 9 + dh * 3 + dw] = s_in[ci][ty + dh][tx + dw];

        const int trev = t_arr[j];
        float a0 = __ldg(temb + trev * 3 + 0);
        float a1 = __ldg(temb + trev * 3 + 1);
        float a2 = __ldg(temb + trev * 3 + 2);
#pragma unroll
        for (int k = 0; k < 27; k++) {
            a0 = fmaf(w[k],      in[k], a0);
            a1 = fmaf(w[27 + k], in[k], a1);
            a2 = fmaf(w[54 + k], in[k], a2);
        }
        const float ec = __ldg(et_coeff + j);
        a0 *= ec; a1 *= ec; a2 *= ec;

        float* Ej = g_E + (size_t)j * PIX;
        Ej[pout]          = a0;
        Ej[HW + pout]     = a1;
        Ej[2 * HW + pout] = a2;
        ps0 += a0; ps1 += a1; ps2 += a2;
        __syncthreads();   // before re-staging shared
    }

    float* Ps = g_Psum + seg * PIX;
    Ps[pout]          = ps0;
    Ps[HW + pout]     = ps1;
    Ps[2 * HW + pout] = ps2;
}

// ---------------------------------------------------------------------------
// Kernel C: per (segment, 128-pixel tile), gather the cross-segment offset
// from g_Psum, then stream the local scan:
//   acc += E[t][p];  out[t+1][p] = alpha_ratio[t]*xT[p] + epc[t]*acc
// Segment-0 blocks also write out[0] = xT.
// ---------------------------------------------------------------------------
__global__ __launch_bounds__(128) void scan_combine_kernel(
    float*       __restrict__ dst,          // (T+1, C, H, W)
    const float* __restrict__ xT,           // first image of original x
    const float* __restrict__ alpha_ratio,  // (T,)
    const float* __restrict__ epc)          // (T,)
{
    const int seg = blockIdx.y;
    const int p   = blockIdx.x * 128 + threadIdx.x;   // < PIX

    float acc = 0.f;
    for (int s = 0; s < seg; s++)
        acc += g_Psum[s * PIX + p];

    const float xv = __ldg(xT + p);
    if (seg == 0)
        dst[p] = xv;                 // image 0 stays xT

    const int t0 = seg * SEGLEN;
#pragma unroll 8
    for (int j = t0; j < t0 + SEGLEN; j++) {
        acc += g_E[(size_t)j * PIX + p];
        dst[(size_t)(j + 1) * PIX + p] = fmaf(__ldg(alpha_ratio + j), xv,
                                              __ldg(epc + j) * acc);
    }
}

extern "C" void kernel_launch(void* const* d_in, const int* in_sizes, int n_in,
                              void* d_out, int out_size)
{
    const float* x           = (const float*)d_in[0];  // (T+1, 3, 64, 64)
    const int*   t_arr       = (const int*)  d_in[1];  // (T,)
    const float* alpha_ratio = (const float*)d_in[2];  // (T,1,1,1)
    const float* et_coeff    = (const float*)d_in[3];  // (T,1,1,1)
    const float* epc         = (const float*)d_in[4];  // (T,1,1,1)
    const float* conv_w      = (const float*)d_in[5];  // (3,3,3,3)
    const float* temb        = (const float*)d_in[6];  // (T, 3)
    float*       out         = (float*)d_out;

    dim3 gA(16, NSEG), bA(256);
    dim3 gC(PIX / 128, NSEG), bC(128);

    for (int it = 0; it < 3; it++) {
        const float* src = (it == 0) ? x : out;  // conv reads images 0..T-1
        conv_partial_kernel<<<gA, bA>>>(src, conv_w, temb, t_arr, et_coeff);
        scan_combine_kernel<<<gC, bC>>>(out, x, alpha_ratio, epc);
    }
}

// round 2
// speedup vs baseline: 1.5369x; 1.5369x over previous
#include <cuda_runtime.h>

#define T_STEPS 1000
#define C_CH    3
#define H_DIM   64
#define W_DIM   64
#define HW      (H_DIM * W_DIM)       // 4096
#define PIX     (C_CH * HW)           // 12288
#define NSEG    25
#define SEGLEN  (T_STEPS / NSEG)      // 40
#define TILE_ROWS 16

// Scratch: et_updated values for one outer iteration, per-segment partial sums.
__device__ float g_E[(size_t)T_STEPS * PIX];      // ~49 MB
__device__ float g_Psum[NSEG * PIX];              // ~1.2 MB

// ---------------------------------------------------------------------------
// Kernel A': one block per (row-tile, image j). Fully parallel over t.
// Stage 3x18x66 halo tile in shared, each thread computes 4 spatial sites
// for all 3 output channels, applies temb[t_rev] and et_coeff[j], stores E.
// ---------------------------------------------------------------------------
__global__ __launch_bounds__(256) void conv_kernel(
    const float* __restrict__ src,       // images 0..T-1, (.., C, H, W)
    const float* __restrict__ conv_w,    // (3,3,3,3) = 81
    const float* __restrict__ temb,      // (T, 3)
    const int*   __restrict__ t_arr,     // (T,)
    const float* __restrict__ et_coeff)  // (T,)
{
    __shared__ float s_in[3][18][66];

    const int j   = blockIdx.y;
    const int r0  = blockIdx.x * TILE_ROWS;
    const int tid = threadIdx.x;

    float w[81];
#pragma unroll
    for (int i = 0; i < 81; i++) w[i] = __ldg(conv_w + i);

    // zero-fill (halo must be zero), then overwrite interior
    {
        float* sf = &s_in[0][0][0];
        for (int l = tid; l < 3 * 18 * 66; l += 256) sf[l] = 0.f;
    }
    __syncthreads();

    const float* img = src + (size_t)j * PIX;
    for (int l = tid; l < 3 * 18 * 64; l += 256) {
        int ci  = l / (18 * 64);
        int rem = l - ci * (18 * 64);
        int r   = rem >> 6;
        int wc  = rem & 63;
        int gh  = r0 + r - 1;
        if (gh >= 0 && gh < H_DIM)
            s_in[ci][r][wc + 1] = img[ci * HW + gh * W_DIM + wc];
    }
    __syncthreads();

    const int   trev = __ldg(t_arr + j);
    const float tb0  = __ldg(temb + trev * 3 + 0);
    const float tb1  = __ldg(temb + trev * 3 + 1);
    const float tb2  = __ldg(temb + trev * 3 + 2);
    const float ec   = __ldg(et_coeff + j);

    float* Ej = g_E + (size_t)j * PIX;

#pragma unroll
    for (int k = 0; k < 4; k++) {
        const int site = tid + 256 * k;       // 0..1023 within tile
        const int h    = site >> 6;           // 0..15
        const int wc   = site & 63;
        float a0 = tb0, a1 = tb1, a2 = tb2;
#pragma unroll
        for (int ci = 0; ci < 3; ci++)
#pragma unroll
            for (int dh = 0; dh < 3; dh++)
#pragma unroll
                for (int dw = 0; dw < 3; dw++) {
                    const float v  = s_in[ci][h + dh][wc + dw];
                    const int   kk = ci * 9 + dh * 3 + dw;
                    a0 = fmaf(w[kk],      v, a0);
                    a1 = fmaf(w[27 + kk], v, a1);
                    a2 = fmaf(w[54 + kk], v, a2);
                }
        const int gpos = (r0 + h) * W_DIM + wc;
        Ej[gpos]           = a0 * ec;
        Ej[HW + gpos]      = a1 * ec;
        Ej[2 * HW + gpos]  = a2 * ec;
    }
}

// ---------------------------------------------------------------------------
// Kernel B': per-segment partial sums of E (E is hot in L2).
// ---------------------------------------------------------------------------
__global__ __launch_bounds__(256) void psum_kernel()
{
    const int p   = blockIdx.x * 256 + threadIdx.x;   // < PIX
    const int seg = blockIdx.y;
    const float* base = g_E + (size_t)seg * SEGLEN * PIX + p;
    float s = 0.f;
#pragma unroll 8
    for (int j = 0; j < SEGLEN; j++)
        s += base[(size_t)j * PIX];
    g_Psum[seg * PIX + p] = s;
}

// ---------------------------------------------------------------------------
// Kernel C: per (segment, pixel), gather cross-segment offset from g_Psum,
// stream the local scan and combine into dst.
// ---------------------------------------------------------------------------
__global__ __launch_bounds__(128) void scan_combine_kernel(
    float*       __restrict__ dst,          // (T+1, C, H, W)
    const float* __restrict__ xT,           // first image of original x
    const float* __restrict__ alpha_ratio,  // (T,)
    const float* __restrict__ epc)          // (T,)
{
    const int seg = blockIdx.y;
    const int p   = blockIdx.x * 128 + threadIdx.x;   // < PIX

    float acc = 0.f;
    for (int s = 0; s < seg; s++)
        acc += g_Psum[s * PIX + p];

    const float xv = __ldg(xT + p);
    if (seg == 0)
        dst[p] = xv;                 // image 0 stays xT

    const int t0 = seg * SEGLEN;
#pragma unroll 8
    for (int j = t0; j < t0 + SEGLEN; j++) {
        acc += g_E[(size_t)j * PIX + p];
        dst[(size_t)(j + 1) * PIX + p] = fmaf(__ldg(alpha_ratio + j), xv,
                                              __ldg(epc + j) * acc);
    }
}

extern "C" void kernel_launch(void* const* d_in, const int* in_sizes, int n_in,
                              void* d_out, int out_size)
{
    const float* x           = (const float*)d_in[0];  // (T+1, 3, 64, 64)
    const int*   t_arr       = (const int*)  d_in[1];  // (T,)
    const float* alpha_ratio = (const float*)d_in[2];  // (T,1,1,1)
    const float* et_coeff    = (const float*)d_in[3];  // (T,1,1,1)
    const float* epc         = (const float*)d_in[4];  // (T,1,1,1)
    const float* conv_w      = (const float*)d_in[5];  // (3,3,3,3)
    const float* temb        = (const float*)d_in[6];  // (T, 3)
    float*       out         = (float*)d_out;

    dim3 gA(H_DIM / TILE_ROWS, T_STEPS), bA(256);      // (4, 1000)
    dim3 gB(PIX / 256, NSEG),            bB(256);      // (48, 25)
    dim3 gC(PIX / 128, NSEG),            bC(128);      // (96, 25)

    for (int it = 0; it < 3; it++) {
        const float* src = (it == 0) ? x : out;  // conv reads images 0..T-1
        conv_kernel<<<gA, bA>>>(src, conv_w, temb, t_arr, et_coeff);
        psum_kernel<<<gB, bB>>>();
        scan_combine_kernel<<<gC, bC>>>(out, x, alpha_ratio, epc);
    }
}

// round 3
// speedup vs baseline: 2.4455x; 1.5912x over previous
#include <cuda_runtime.h>

#define T_STEPS 1000
#define C_CH    3
#define H_DIM   64
#define W_DIM   64
#define HW      (H_DIM * W_DIM)       // 4096
#define PIX     (C_CH * HW)           // 12288
#define NSEG    25
#define SEGLEN  (T_STEPS / NSEG)      // 40
#define TILE_ROWS 16

__device__ float g_E[(size_t)T_STEPS * PIX];      // ~49 MB scratch
__device__ float g_Psum[NSEG * PIX];              // ~1.2 MB

// ---------------------------------------------------------------------------
// Kernel A: one block per (16-row tile, image j). Thread = one column, 4
// adjacent rows, all 3 output channels => 12 independent FMA accumulators.
// Weights live in shared (broadcast LDS); ci loop NOT unrolled so only ~27
// weights + 18 inputs are register-live at a time.
// ---------------------------------------------------------------------------
__global__ __launch_bounds__(256, 3) void conv_kernel(
    const float* __restrict__ src,       // images 0..T-1, (.., C, H, W)
    const float* __restrict__ conv_w,    // (3,3,3,3) = 81
    const float* __restrict__ temb,      // (T, 3)
    const int*   __restrict__ t_arr,     // (T,)
    const float* __restrict__ et_coeff)  // (T,)
{
    __shared__ float s_in[3][18][66];    // row 0 = global row r0-1; col 0 = col -1
    __shared__ float s_w[81];

    const int j   = blockIdx.y;
    const int r0  = blockIdx.x * TILE_ROWS;
    const int tid = threadIdx.x;
    const int wc  = tid & 63;            // column 0..63
    const int rg  = tid >> 6;            // row-group 0..3 -> rows rg*4..rg*4+3

    if (tid < 81) s_w[tid] = conv_w[tid];

    // Stage halo tile in one predicated pass (halo & pad cols read as 0).
    const float* img = src + (size_t)j * PIX;
    for (int l = tid; l < 3 * 18 * 66; l += 256) {
        int ci  = l / (18 * 66);
        int rem = l - ci * (18 * 66);
        int r   = rem / 66;
        int cc  = rem - r * 66;
        int gh  = r0 + r - 1;
        int gw  = cc - 1;
        float v = 0.f;
        if (gh >= 0 && gh < H_DIM && gw >= 0 && gw < W_DIM)
            v = img[ci * HW + gh * W_DIM + gw];
        (&s_in[0][0][0])[l] = v;
    }
    __syncthreads();

    const int   trev = __ldg(t_arr + j);
    const float ec   = __ldg(et_coeff + j);

    float acc[3][4];
#pragma unroll
    for (int c = 0; c < 3; c++) {
        const float tb = __ldg(temb + trev * 3 + c);
#pragma unroll
        for (int s = 0; s < 4; s++) acc[c][s] = tb;
    }

#pragma unroll 1
    for (int ci = 0; ci < 3; ci++) {
        // 6 halo rows x 3 cols feed 4 sites (rows rg*4+0..3)
        float v[6][3];
#pragma unroll
        for (int r = 0; r < 6; r++)
#pragma unroll
            for (int d = 0; d < 3; d++)
                v[r][d] = s_in[ci][rg * 4 + r][wc + d];

#pragma unroll
        for (int dh = 0; dh < 3; dh++)
#pragma unroll
            for (int dw = 0; dw < 3; dw++) {
                const float w0 = s_w[      ci * 9 + dh * 3 + dw];
                const float w1 = s_w[27 + ci * 9 + dh * 3 + dw];
                const float w2 = s_w[54 + ci * 9 + dh * 3 + dw];
#pragma unroll
                for (int s = 0; s < 4; s++) {
                    const float x = v[s + dh][dw];
                    acc[0][s] = fmaf(w0, x, acc[0][s]);
                    acc[1][s] = fmaf(w1, x, acc[1][s]);
                    acc[2][s] = fmaf(w2, x, acc[2][s]);
                }
            }
    }

    float* Ej = g_E + (size_t)j * PIX;
#pragma unroll
    for (int s = 0; s < 4; s++) {
        const int gpos = (r0 + rg * 4 + s) * W_DIM + wc;
        Ej[gpos]          = acc[0][s] * ec;
        Ej[HW + gpos]     = acc[1][s] * ec;
        Ej[2 * HW + gpos] = acc[2][s] * ec;
    }
}

// ---------------------------------------------------------------------------
// Kernel B: per-segment partial sums of E (float4, E hot in L2).
// ---------------------------------------------------------------------------
__global__ __launch_bounds__(256) void psum_kernel()
{
    const int p4  = blockIdx.x * 256 + threadIdx.x;   // < PIX/4
    const int seg = blockIdx.y;
    const float4* base = (const float4*)g_E + (size_t)seg * SEGLEN * (PIX / 4) + p4;
    float4 s = make_float4(0.f, 0.f, 0.f, 0.f);
#pragma unroll 8
    for (int j = 0; j < SEGLEN; j++) {
        float4 e = base[(size_t)j * (PIX / 4)];
        s.x += e.x; s.y += e.y; s.z += e.z; s.w += e.w;
    }
    ((float4*)g_Psum)[seg * (PIX / 4) + p4] = s;
}

// ---------------------------------------------------------------------------
// Kernel C: cross-segment offset + local scan + combine (float4).
// ---------------------------------------------------------------------------
__global__ __launch_bounds__(128) void scan_combine_kernel(
    float*       __restrict__ dst,          // (T+1, C, H, W)
    const float* __restrict__ xT,           // first image of original x
    const float* __restrict__ alpha_ratio,  // (T,)
    const float* __restrict__ epc)          // (T,)
{
    const int seg = blockIdx.y;
    const int p4  = blockIdx.x * 128 + threadIdx.x;   // < PIX/4

    float4 acc = make_float4(0.f, 0.f, 0.f, 0.f);
    for (int s = 0; s < seg; s++) {
        float4 ps = ((const float4*)g_Psum)[s * (PIX / 4) + p4];
        acc.x += ps.x; acc.y += ps.y; acc.z += ps.z; acc.w += ps.w;
    }

    const float4 xv = ((const float4*)xT)[p4];
    if (seg == 0)
        ((float4*)dst)[p4] = xv;             // image 0 stays xT

    const int t0 = seg * SEGLEN;
#pragma unroll 4
    for (int j = t0; j < t0 + SEGLEN; j++) {
        float4 e = ((const float4*)g_E)[(size_t)j * (PIX / 4) + p4];
        acc.x += e.x; acc.y += e.y; acc.z += e.z; acc.w += e.w;
        const float ar = __ldg(alpha_ratio + j);
        const float ep = __ldg(epc + j);
        float4 o;
        o.x = fmaf(ar, xv.x, ep * acc.x);
        o.y = fmaf(ar, xv.y, ep * acc.y);
        o.z = fmaf(ar, xv.z, ep * acc.z);
        o.w = fmaf(ar, xv.w, ep * acc.w);
        ((float4*)dst)[(size_t)(j + 1) * (PIX / 4) + p4] = o;
    }
}

extern "C" void kernel_launch(void* const* d_in, const int* in_sizes, int n_in,
                              void* d_out, int out_size)
{
    const float* x           = (const float*)d_in[0];  // (T+1, 3, 64, 64)
    const int*   t_arr       = (const int*)  d_in[1];  // (T,)
    const float* alpha_ratio = (const float*)d_in[2];  // (T,1,1,1)
    const float* et_coeff    = (const float*)d_in[3];  // (T,1,1,1)
    const float* epc         = (const float*)d_in[4];  // (T,1,1,1)
    const float* conv_w      = (const float*)d_in[5];  // (3,3,3,3)
    const float* temb        = (const float*)d_in[6];  // (T, 3)
    float*       out         = (float*)d_out;

    dim3 gA(H_DIM / TILE_ROWS, T_STEPS), bA(256);      // (4, 1000)
    dim3 gB(PIX / 4 / 256, NSEG),        bB(256);      // (12, 25)
    dim3 gC(PIX / 4 / 128, NSEG),        bC(128);      // (24, 25)

    for (int it = 0; it < 3; it++) {
        const float* src = (it == 0) ? x : out;  // conv reads images 0..T-1
        conv_kernel<<<gA, bA>>>(src, conv_w, temb, t_arr, et_coeff);
        psum_kernel<<<gB, bB>>>();
        scan_combine_kernel<<<gC, bC>>>(out, x, alpha_ratio, epc);
    }
}

// round 4
// speedup vs baseline: 3.6065x; 1.4747x over previous
#include <cuda_runtime.h>

#define T_STEPS 1000
#define C_CH    3
#define H_DIM   64
#define W_DIM   64
#define HW      (H_DIM * W_DIM)       // 4096
#define PIX     (C_CH * HW)           // 12288
#define PIX4    (PIX / 4)             // 3072
#define NSEG    40
#define SEGLEN  (T_STEPS / NSEG)      // 25
#define TILE_ROWS 16

__device__ float g_E[(size_t)T_STEPS * PIX];      // ~49 MB scratch
__device__ float g_Psum[NSEG * PIX];              // ~2 MB

// ---------------------------------------------------------------------------
// Kernel A: block = (16-row tile, image j). Thread = 1 row x 4 consecutive
// cols x 3 output channels (12 accumulators). All shared traffic is 128-bit:
//  - input tile rows padded to 72 floats (global col c -> float idx c+4)
//  - weights transposed to float4 (w_co0,w_co1,w_co2,0), pre-scaled by et_coeff
// ---------------------------------------------------------------------------
__global__ __launch_bounds__(256, 4) void conv_kernel(
    const float* __restrict__ src,       // images 0..T-1, (.., C, H, W)
    const float* __restrict__ conv_w,    // (3,3,3,3) = 81
    const float* __restrict__ temb,      // (T, 3)
    const int*   __restrict__ t_arr,     // (T,)
    const float* __restrict__ et_coeff)  // (T,)
{
    __shared__ float4 s_in4[3][18][18];  // [ci][row][quad]; quad q+1 = global cols 4q..4q+3
    __shared__ float4 s_wt[3][9];        // [ci][tap] = (w0,w1,w2,0) * ec

    const int j   = blockIdx.y;
    const int r0  = blockIdx.x * TILE_ROWS;
    const int tid = threadIdx.x;
    const int h   = tid >> 4;            // row 0..15
    const int k   = tid & 15;            // col-group 0..15 (cols 4k..4k+3)
    const float ec = __ldg(et_coeff + j);

    if (tid < 27) {
        // tid = ci*9 + tap ; weight index co*27 + tid
        float4 w;
        w.x = conv_w[tid]      * ec;
        w.y = conv_w[27 + tid] * ec;
        w.z = conv_w[54 + tid] * ec;
        w.w = 0.f;
        ((float4*)s_wt)[tid] = w;
    }

    // zero-fill (halo + pads must be 0)
    {
        float4 z = make_float4(0.f, 0.f, 0.f, 0.f);
        float4* sf = &s_in4[0][0][0];
        for (int l = tid; l < 3 * 18 * 18; l += 256) sf[l] = z;
    }
    __syncthreads();

    // interior fill: 54 (ci,row) rows x 16 quads, all LDG.128/STS.128
    const float4* img4 = (const float4*)(src + (size_t)j * PIX);
    for (int l = tid; l < 3 * 18 * 16; l += 256) {
        int rowid = l >> 4;                 // 0..53
        int q     = l & 15;
        int ci    = rowid / 18;
        int r     = rowid - ci * 18;
        int gh    = r0 + r - 1;
        if (gh >= 0 && gh < H_DIM)
            s_in4[ci][r][q + 1] = img4[ci * (HW / 4) + gh * 16 + q];
    }
    __syncthreads();

    const int trev = __ldg(t_arr + j);
    float acc[3][4];
#pragma unroll
    for (int c = 0; c < 3; c++) {
        const float tb = __ldg(temb + trev * 3 + c) * ec;
#pragma unroll
        for (int s = 0; s < 4; s++) acc[c][s] = tb;
    }

#pragma unroll 1
    for (int ci = 0; ci < 3; ci++) {
        // 3 input rows x 6 cols (global cols 4k-1 .. 4k+4) via 3 LDS.128/row
        float v[3][6];
#pragma unroll
        for (int r = 0; r < 3; r++) {
            float4 A = s_in4[ci][h + r][k];
            float4 B = s_in4[ci][h + r][k + 1];
            float4 C = s_in4[ci][h + r][k + 2];
            v[r][0] = A.w; v[r][1] = B.x; v[r][2] = B.y;
            v[r][3] = B.z; v[r][4] = B.w; v[r][5] = C.x;
        }
#pragma unroll
        for (int dh = 0; dh < 3; dh++)
#pragma unroll
            for (int dw = 0; dw < 3; dw++) {
                const float4 wv = s_wt[ci][dh * 3 + dw];
#pragma unroll
                for (int s = 0; s < 4; s++) {
                    const float xv = v[dh][dw + s];
                    acc[0][s] = fmaf(wv.x, xv, acc[0][s]);
                    acc[1][s] = fmaf(wv.y, xv, acc[1][s]);
                    acc[2][s] = fmaf(wv.z, xv, acc[2][s]);
                }
            }
    }

    float4* Ej4 = (float4*)(g_E + (size_t)j * PIX);
    const int gq = (r0 + h) * 16 + k;     // float4 index within a channel plane
    Ej4[gq]                = make_float4(acc[0][0], acc[0][1], acc[0][2], acc[0][3]);
    Ej4[(HW / 4) + gq]     = make_float4(acc[1][0], acc[1][1], acc[1][2], acc[1][3]);
    Ej4[2 * (HW / 4) + gq] = make_float4(acc[2][0], acc[2][1], acc[2][2], acc[2][3]);
}

// ---------------------------------------------------------------------------
// Kernel B: per-segment partial sums of E (float4, E hot in L2).
// ---------------------------------------------------------------------------
__global__ __launch_bounds__(256) void psum_kernel()
{
    const int p4  = blockIdx.x * 256 + threadIdx.x;   // < PIX4
    const int seg = blockIdx.y;
    const float4* base = (const float4*)g_E + (size_t)seg * SEGLEN * PIX4 + p4;
    float4 s = make_float4(0.f, 0.f, 0.f, 0.f);
#pragma unroll 5
    for (int j = 0; j < SEGLEN; j++) {
        float4 e = base[(size_t)j * PIX4];
        s.x += e.x; s.y += e.y; s.z += e.z; s.w += e.w;
    }
    ((float4*)g_Psum)[seg * PIX4 + p4] = s;
}

// ---------------------------------------------------------------------------
// Kernel C: cross-segment offset + local scan + combine (float4).
// ---------------------------------------------------------------------------
__global__ __launch_bounds__(128) void scan_combine_kernel(
    float*       __restrict__ dst,          // (T+1, C, H, W)
    const float* __restrict__ xT,           // first image of original x
    const float* __restrict__ alpha_ratio,  // (T,)
    const float* __restrict__ epc)          // (T,)
{
    const int seg = blockIdx.y;
    const int p4  = blockIdx.x * 128 + threadIdx.x;   // < PIX4

    float4 acc = make_float4(0.f, 0.f, 0.f, 0.f);
    for (int s = 0; s < seg; s++) {
        float4 ps = ((const float4*)g_Psum)[s * PIX4 + p4];
        acc.x += ps.x; acc.y += ps.y; acc.z += ps.z; acc.w += ps.w;
    }

    const float4 xv = ((const float4*)xT)[p4];
    if (seg == 0)
        ((float4*)dst)[p4] = xv;             // image 0 stays xT

    const int t0 = seg * SEGLEN;
#pragma unroll 5
    for (int j = t0; j < t0 + SEGLEN; j++) {
        float4 e = ((const float4*)g_E)[(size_t)j * PIX4 + p4];
        acc.x += e.x; acc.y += e.y; acc.z += e.z; acc.w += e.w;
        const float ar = __ldg(alpha_ratio + j);
        const float ep = __ldg(epc + j);
        float4 o;
        o.x = fmaf(ar, xv.x, ep * acc.x);
        o.y = fmaf(ar, xv.y, ep * acc.y);
        o.z = fmaf(ar, xv.z, ep * acc.z);
        o.w = fmaf(ar, xv.w, ep * acc.w);
        ((float4*)dst)[(size_t)(j + 1) * PIX4 + p4] = o;
    }
}

extern "C" void kernel_launch(void* const* d_in, const int* in_sizes, int n_in,
                              void* d_out, int out_size)
{
    const float* x           = (const float*)d_in[0];  // (T+1, 3, 64, 64)
    const int*   t_arr       = (const int*)  d_in[1];  // (T,)
    const float* alpha_ratio = (const float*)d_in[2];  // (T,1,1,1)
    const float* et_coeff    = (const float*)d_in[3];  // (T,1,1,1)
    const float* epc         = (const float*)d_in[4];  // (T,1,1,1)
    const float* conv_w      = (const float*)d_in[5];  // (3,3,3,3)
    const float* temb        = (const float*)d_in[6];  // (T, 3)
    float*       out         = (float*)d_out;

    dim3 gA(H_DIM / TILE_ROWS, T_STEPS), bA(256);      // (4, 1000)
    dim3 gB(PIX4 / 256, NSEG),           bB(256);      // (12, 40)
    dim3 gC(PIX4 / 128, NSEG),           bC(128);      // (24, 40)

    for (int it = 0; it < 3; it++) {
        const float* src = (it == 0) ? x : out;  // conv reads images 0..T-1
        conv_kernel<<<gA, bA>>>(src, conv_w, temb, t_arr, et_coeff);
        psum_kernel<<<gB, bB>>>();
        scan_combine_kernel<<<gC, bC>>>(out, x, alpha_ratio, epc);
    }
}